// round 1
// baseline (speedup 1.0000x reference)
#include <cuda_runtime.h>
#include <math.h>

#define BB 8
#define LL 1024
#define DM 512
#define HH 8
#define HD 64
#define DFF 2048
#define BLN (BB*LL)
#define MAXK 50

// ---------------- scratch (device globals; no allocations allowed) ----------
__device__ float g_q [BLN*DM];
__device__ float g_k [BLN*DM];
__device__ float g_v [BLN*DM];
__device__ float g_t0[BLN*DM];
__device__ float g_x1[BLN*DM];
__device__ float g_x2[BLN*DM];
__device__ float g_g [BLN*DM];
__device__ float g_hid[(size_t)BLN*DFF];
__device__ float g_xg[BB*DM];
__device__ float g_w [BB*MAXK];
__device__ int   g_kk[BB];

// ---------------- generic SGEMM: C = epi(A @ B) -----------------------------
// A: [M,K] row-major. TRANSB=false: B [K,N]; TRANSB=true: B stored [N,K].
// EPI: 0: +bias | 1: aux + sc*(acc+bias) | 2: aux * sigmoid(acc+bias)
//      3: relu(acc) | 4: aux + sc*acc
template<int EPI, bool TRANSB>
__global__ void __launch_bounds__(256) sgemm128(const float* __restrict__ A,
                                                const float* __restrict__ Bm,
                                                const float* __restrict__ bias,
                                                const float* __restrict__ aux,
                                                const float* __restrict__ scale,
                                                float* __restrict__ C,
                                                int M, int N, int K)
{
    __shared__ float As[8][128];
    __shared__ float Bs[8][128];
    const int tid = threadIdx.x;
    const int rowBase = blockIdx.y * 128;
    const int colBase = blockIdx.x * 128;
    const int tr = tid >> 4, tc = tid & 15;
    float acc[8][8];
#pragma unroll
    for (int i = 0; i < 8; i++)
#pragma unroll
        for (int j = 0; j < 8; j++) acc[i][j] = 0.f;

    const int ar  = tid >> 1;
    const int ac4 = (tid & 1) * 4;
    for (int k0 = 0; k0 < K; k0 += 8) {
        float4 av = *(const float4*)(A + (size_t)(rowBase + ar) * K + k0 + ac4);
        As[ac4+0][ar] = av.x; As[ac4+1][ar] = av.y;
        As[ac4+2][ar] = av.z; As[ac4+3][ar] = av.w;
        if (TRANSB) {
            float4 bv = *(const float4*)(Bm + (size_t)(colBase + ar) * K + k0 + ac4);
            Bs[ac4+0][ar] = bv.x; Bs[ac4+1][ar] = bv.y;
            Bs[ac4+2][ar] = bv.z; Bs[ac4+3][ar] = bv.w;
        } else {
            int br  = tid >> 5;
            int bc4 = (tid & 31) * 4;
            *(float4*)&Bs[br][bc4] =
                *(const float4*)(Bm + (size_t)(k0 + br) * N + colBase + bc4);
        }
        __syncthreads();
#pragma unroll
        for (int kk = 0; kk < 8; kk++) {
            float4 a0 = *(const float4*)&As[kk][tr*8];
            float4 a1 = *(const float4*)&As[kk][tr*8+4];
            float4 b0 = *(const float4*)&Bs[kk][tc*8];
            float4 b1 = *(const float4*)&Bs[kk][tc*8+4];
            float a[8]  = {a0.x,a0.y,a0.z,a0.w,a1.x,a1.y,a1.z,a1.w};
            float bbv[8]= {b0.x,b0.y,b0.z,b0.w,b1.x,b1.y,b1.z,b1.w};
#pragma unroll
            for (int i = 0; i < 8; i++)
#pragma unroll
                for (int j = 0; j < 8; j++)
                    acc[i][j] = fmaf(a[i], bbv[j], acc[i][j]);
        }
        __syncthreads();
    }
    float sc = 1.f;
    if constexpr (EPI == 1 || EPI == 4) sc = *scale;
#pragma unroll
    for (int i = 0; i < 8; i++) {
        int m = rowBase + tr*8 + i;
#pragma unroll
        for (int j = 0; j < 8; j++) {
            int n = colBase + tc*8 + j;
            size_t idx = (size_t)m * N + n;
            float vv = acc[i][j];
            if constexpr (EPI == 0) vv += bias[n];
            else if constexpr (EPI == 1) vv = aux[idx] + sc * (vv + bias[n]);
            else if constexpr (EPI == 2) vv = aux[idx] / (1.f + expf(-(vv + bias[n])));
            else if constexpr (EPI == 3) vv = fmaxf(vv, 0.f);
            else if constexpr (EPI == 4) vv = aux[idx] + sc * vv;
            C[idx] = vv;
        }
    }
}

// ---------------- attention scores: s[b,h,i,j] = q.k/8 ----------------------
__global__ void __launch_bounds__(256) attn_scores_kern(const float* __restrict__ q,
                                                        const float* __restrict__ k,
                                                        float* __restrict__ s)
{
    const int bh = blockIdx.z;
    const int b  = bh >> 3, h = bh & 7;
    const int i0 = blockIdx.y * 64, j0 = blockIdx.x * 64;
    __shared__ float Qs[64][65];
    __shared__ float Ks[64][65];
    const int tid = threadIdx.x;
#pragma unroll
    for (int it = 0; it < 4; it++) {
        int t  = tid + it * 256;         // 0..1023
        int r  = t >> 4;                 // 0..63
        int c4 = (t & 15) * 4;
        float4 qv = *(const float4*)(q + (size_t)(b*LL + i0 + r) * DM + h*HD + c4);
        Qs[c4+0][r] = qv.x; Qs[c4+1][r] = qv.y; Qs[c4+2][r] = qv.z; Qs[c4+3][r] = qv.w;
        float4 kv = *(const float4*)(k + (size_t)(b*LL + j0 + r) * DM + h*HD + c4);
        Ks[c4+0][r] = kv.x; Ks[c4+1][r] = kv.y; Ks[c4+2][r] = kv.z; Ks[c4+3][r] = kv.w;
    }
    __syncthreads();
    const int tr = tid >> 4, tc = tid & 15;
    float acc[4][4] = {};
#pragma unroll
    for (int kk = 0; kk < 64; kk++) {
        float a[4], bv[4];
#pragma unroll
        for (int i = 0; i < 4; i++) a[i]  = Qs[kk][tr*4 + i];
#pragma unroll
        for (int j = 0; j < 4; j++) bv[j] = Ks[kk][tc*4 + j];
#pragma unroll
        for (int i = 0; i < 4; i++)
#pragma unroll
            for (int j = 0; j < 4; j++)
                acc[i][j] = fmaf(a[i], bv[j], acc[i][j]);
    }
#pragma unroll
    for (int i = 0; i < 4; i++)
#pragma unroll
        for (int j = 0; j < 4; j++)
            s[((size_t)bh*LL + i0 + tr*4 + i) * LL + j0 + tc*4 + j] = acc[i][j] * 0.125f;
}

// ---------------- in-place row softmax over 1024 ----------------------------
__global__ void __launch_bounds__(256) softmax1024(float* __restrict__ a)
{
    size_t row = blockIdx.x;
    float4* p  = (float4*)(a + row * 1024);
    int t = threadIdx.x;
    float4 v = p[t];
    float m = fmaxf(fmaxf(v.x, v.y), fmaxf(v.z, v.w));
#pragma unroll
    for (int o = 16; o; o >>= 1) m = fmaxf(m, __shfl_xor_sync(~0u, m, o));
    __shared__ float sm[8], ss[8];
    int w = t >> 5, ln = t & 31;
    if (ln == 0) sm[w] = m;
    __syncthreads();
    m = sm[0];
#pragma unroll
    for (int i = 1; i < 8; i++) m = fmaxf(m, sm[i]);
    float e0 = __expf(v.x - m), e1 = __expf(v.y - m);
    float e2 = __expf(v.z - m), e3 = __expf(v.w - m);
    float su = e0 + e1 + e2 + e3;
#pragma unroll
    for (int o = 16; o; o >>= 1) su += __shfl_xor_sync(~0u, su, o);
    if (ln == 0) ss[w] = su;
    __syncthreads();
    float tot = 0.f;
#pragma unroll
    for (int i = 0; i < 8; i++) tot += ss[i];
    float inv = 1.f / tot;
    p[t] = make_float4(e0*inv, e1*inv, e2*inv, e3*inv);
}

// ---------------- o[b,i,h,:] = attn[b,h,i,:] @ v[b,:,h,:] -------------------
__global__ void __launch_bounds__(256) attn_v_kern(const float* __restrict__ p,
                                                   const float* __restrict__ v,
                                                   float* __restrict__ o)
{
    const int bh = blockIdx.y;
    const int b  = bh >> 3, h = bh & 7;
    const int i0 = blockIdx.x * 64;
    __shared__ float As[32][65];
    __shared__ float Bs[32][64];
    const int tid = threadIdx.x;
    const int tr = tid >> 4, tc = tid & 15;
    float acc[4][4] = {};
    for (int k0 = 0; k0 < LL; k0 += 32) {
#pragma unroll
        for (int it = 0; it < 2; it++) {
            int t  = tid + it * 256;      // 0..511
            int r  = t >> 3;              // 0..63
            int c4 = (t & 7) * 4;
            float4 av = *(const float4*)(p + ((size_t)bh*LL + i0 + r) * LL + k0 + c4);
            As[c4+0][r] = av.x; As[c4+1][r] = av.y;
            As[c4+2][r] = av.z; As[c4+3][r] = av.w;
        }
#pragma unroll
        for (int it = 0; it < 2; it++) {
            int t  = tid + it * 256;
            int r  = t >> 4;              // 0..31
            int c4 = (t & 15) * 4;
            *(float4*)&Bs[r][c4] =
                *(const float4*)(v + (size_t)(b*LL + k0 + r) * DM + h*HD + c4);
        }
        __syncthreads();
#pragma unroll
        for (int kk = 0; kk < 32; kk++) {
            float a[4], bv[4];
#pragma unroll
            for (int i = 0; i < 4; i++) a[i]  = As[kk][tr*4 + i];
#pragma unroll
            for (int j = 0; j < 4; j++) bv[j] = Bs[kk][tc*4 + j];
#pragma unroll
            for (int i = 0; i < 4; i++)
#pragma unroll
                for (int j = 0; j < 4; j++)
                    acc[i][j] = fmaf(a[i], bv[j], acc[i][j]);
        }
        __syncthreads();
    }
#pragma unroll
    for (int i = 0; i < 4; i++)
#pragma unroll
        for (int j = 0; j < 4; j++)
            o[(size_t)(b*LL + i0 + tr*4 + i) * DM + h*HD + tc*4 + j] = acc[i][j];
}

// ---------------- mean over L --------------------------------------------
__global__ void __launch_bounds__(512) col_mean(const float* __restrict__ x,
                                                float* __restrict__ xg)
{
    int b = blockIdx.x, d = threadIdx.x;
    const float* p = x + (size_t)b * LL * DM + d;
    float s = 0.f;
#pragma unroll 8
    for (int t = 0; t < LL; t++) s += p[(size_t)t * DM];
    xg[b*DM + d] = s * (1.0f / (float)LL);
}

// ---------------- kernel-size predictor + masked softmax of taps ----------
__global__ void __launch_bounds__(256) kernel_pred(const float* __restrict__ xg,
                                                   const float* __restrict__ w1,
                                                   const float* __restrict__ b1,
                                                   const float* __restrict__ w2,
                                                   const float* __restrict__ b2,
                                                   const float* __restrict__ tw,
                                                   float* __restrict__ wout,
                                                   int* __restrict__ kout)
{
    int b = blockIdx.x, j = threadIdx.x;
    __shared__ float xs[DM];
    xs[j]       = xg[b*DM + j];
    xs[j + 256] = xg[b*DM + j + 256];
    __syncthreads();
    float hj = b1[j];
#pragma unroll 4
    for (int d = 0; d < DM; d++) hj = fmaf(xs[d], w1[d*256 + j], hj);
    hj = fmaxf(hj, 0.f) * w2[j];
    __shared__ float red[256];
    red[j] = hj;
    __syncthreads();
    for (int s = 128; s; s >>= 1) { if (j < s) red[j] += red[j + s]; __syncthreads(); }
    if (j == 0) {
        float sv = 1.f / (1.f + expf(-(red[0] + b2[0])));
        int kk = (int)rintf(sv * 45.f + 5.f);   // round-half-even, matches jnp.round
        kk = max(5, min(kk, MAXK));             // min(MAX_K, L//3)=50
        kout[b] = kk;
        float m = -3.4e38f;
        for (int i = 0; i < kk; i++) m = fmaxf(m, tw[i]);
        float e[MAXK], su = 0.f;
        for (int i = 0; i < kk; i++) { e[i] = expf(tw[i] - m); su += e[i]; }
        float inv = 1.f / su;
        for (int i = 0; i < MAXK; i++) wout[b*MAXK + i] = (i < kk) ? e[i] * inv : 0.f;
    }
}

// ---------------- seasonal = x - depthwise-conv trend (replicate pad) ------
__global__ void __launch_bounds__(512) decomp_kern(const float* __restrict__ x,
                                                   const float* __restrict__ w,
                                                   const int* __restrict__ kk,
                                                   float* __restrict__ out)
{
    int b = blockIdx.y, t = blockIdx.x, d = threadIdx.x;
    int k = kk[b];
    int base = t - (k >> 1);
    const float* wb = w + b*MAXK;
    const float* xb = x + (size_t)b * LL * DM;
    float acc = 0.f;
    for (int i = 0; i < k; i++) {
        int tc = base + i;
        tc = tc < 0 ? 0 : (tc > LL-1 ? LL-1 : tc);
        acc = fmaf(wb[i], xb[(size_t)tc * DM + d], acc);
    }
    size_t o = (size_t)(b*LL + t) * DM + d;
    out[o] = x[o] - acc;
}

// ---------------------------------------------------------------------------
extern "C" void kernel_launch(void* const* d_in, const int* in_sizes, int n_in,
                              void* d_out, int out_size)
{
    const float* x       = (const float*)d_in[0];
    const float* Wq      = (const float*)d_in[1];
    const float* bq      = (const float*)d_in[2];
    const float* Wk      = (const float*)d_in[3];
    const float* bk      = (const float*)d_in[4];
    const float* Wv      = (const float*)d_in[5];
    const float* bv      = (const float*)d_in[6];
    const float* Wo      = (const float*)d_in[7];
    const float* bo      = (const float*)d_in[8];
    const float* gate_w  = (const float*)d_in[9];
    const float* gate_b  = (const float*)d_in[10];
    const float* conv1_w = (const float*)d_in[11];
    const float* conv2_w = (const float*)d_in[12];
    const float* tw1     = (const float*)d_in[13];
    const float* kp1_w1  = (const float*)d_in[14];
    const float* kp1_b1  = (const float*)d_in[15];
    const float* kp1_w2  = (const float*)d_in[16];
    const float* kp1_b2  = (const float*)d_in[17];
    const float* tw2     = (const float*)d_in[18];
    const float* kp2_w1  = (const float*)d_in[19];
    const float* kp2_b1  = (const float*)d_in[20];
    const float* kp2_w2  = (const float*)d_in[21];
    const float* kp2_b2  = (const float*)d_in[22];
    const float* attn_sc = (const float*)d_in[23];
    const float* ffn_sc  = (const float*)d_in[24];

    float* res  = (float*)d_out;                          // [B,L,D]
    float* attn = (float*)d_out + (size_t)BB*LL*DM;       // [B,H,L,L]

    float *q, *k, *v, *t0, *x1, *x2, *gg, *hid, *xg, *wb;
    int* kb;
    cudaGetSymbolAddress((void**)&q,   g_q);
    cudaGetSymbolAddress((void**)&k,   g_k);
    cudaGetSymbolAddress((void**)&v,   g_v);
    cudaGetSymbolAddress((void**)&t0,  g_t0);
    cudaGetSymbolAddress((void**)&x1,  g_x1);
    cudaGetSymbolAddress((void**)&x2,  g_x2);
    cudaGetSymbolAddress((void**)&gg,  g_g);
    cudaGetSymbolAddress((void**)&hid, g_hid);
    cudaGetSymbolAddress((void**)&xg,  g_xg);
    cudaGetSymbolAddress((void**)&wb,  g_w);
    cudaGetSymbolAddress((void**)&kb,  g_kk);

    const dim3 blk(256);

    // QKV projections
    sgemm128<0,false><<<dim3(4,64), blk>>>(x, Wq, bq, nullptr, nullptr, q, BLN, DM, DM);
    sgemm128<0,false><<<dim3(4,64), blk>>>(x, Wk, bk, nullptr, nullptr, k, BLN, DM, DM);
    sgemm128<0,false><<<dim3(4,64), blk>>>(x, Wv, bv, nullptr, nullptr, v, BLN, DM, DM);

    // scores -> softmax (in the output attn region) -> AV
    attn_scores_kern<<<dim3(16,16,BB*HH), blk>>>(q, k, attn);
    softmax1024<<<BB*HH*LL, blk>>>(attn);
    attn_v_kern<<<dim3(16,BB*HH), blk>>>(attn, v, t0);

    // out proj + residual: x1 = x + attn_scale*(t0@Wo + bo)
    sgemm128<1,false><<<dim3(4,64), blk>>>(t0, Wo, bo, x, attn_sc, x1, BLN, DM, DM);

    // decomp 1: x2 = seasonal(x1)
    col_mean<<<BB, 512>>>(x1, xg);
    kernel_pred<<<BB, 256>>>(xg, kp1_w1, kp1_b1, kp1_w2, kp1_b2, tw1, wb, kb);
    decomp_kern<<<dim3(LL,BB), 512>>>(x1, wb, kb, x2);

    // FFN: gate -> conv1(relu) -> conv2 + residual
    sgemm128<2,true><<<dim3(4,64),  blk>>>(x2,  gate_w,  gate_b, x2, nullptr, gg,  BLN, DM,  DM);
    sgemm128<3,true><<<dim3(16,64), blk>>>(gg,  conv1_w, nullptr, nullptr, nullptr, hid, BLN, DFF, DM);
    sgemm128<4,true><<<dim3(4,64),  blk>>>(hid, conv2_w, nullptr, x2, ffn_sc, x1, BLN, DM, DFF);

    // decomp 2 -> res (directly into d_out)
    col_mean<<<BB, 512>>>(x1, xg);
    kernel_pred<<<BB, 256>>>(xg, kp2_w1, kp2_b1, kp2_w2, kp2_b2, tw2, wb, kb);
    decomp_kern<<<dim3(LL,BB), 512>>>(x1, wb, kb, res);
}

// round 2
// speedup vs baseline: 1.6827x; 1.6827x over previous
#include <cuda_runtime.h>
#include <math.h>

#define BB 8
#define LL 1024
#define DM 512
#define HH 8
#define HD 64
#define DFF 2048
#define BLN (BB*LL)
#define MAXK 50

// ---------------- scratch (device globals; no allocations allowed) ----------
__device__ float g_q [BLN*DM];
__device__ float g_k [BLN*DM];
__device__ float g_v [BLN*DM];
__device__ float g_t0[BLN*DM];
__device__ float g_x1[BLN*DM];
__device__ float g_x2[BLN*DM];
__device__ float g_g [BLN*DM];
__device__ float g_hid[(size_t)BLN*DFF];
__device__ float g_xg[BB*DM];
__device__ float g_w [BB*MAXK];
__device__ int   g_kk[BB];

// ---------------- helpers ----------------------------------------------------
__device__ __forceinline__ unsigned f2tf(float x) {
    unsigned r;
    asm("cvt.rna.tf32.f32 %0, %1;" : "=r"(r) : "f"(x));
    return r;
}

__device__ __forceinline__ void mma_tf32(float c[4], const unsigned a[4], const unsigned b[2]) {
    asm volatile(
        "mma.sync.aligned.m16n8k8.row.col.f32.tf32.tf32.f32 "
        "{%0,%1,%2,%3},{%4,%5,%6,%7},{%8,%9},{%0,%1,%2,%3};"
        : "+f"(c[0]), "+f"(c[1]), "+f"(c[2]), "+f"(c[3])
        : "r"(a[0]), "r"(a[1]), "r"(a[2]), "r"(a[3]), "r"(b[0]), "r"(b[1]));
}

// ---------------- tf32 tensor-core GEMM --------------------------------------
// C[M,N] = epi(alpha * A[M,K] @ B) ; TRANSB ? B stored [N,K] : [K,N]
// Batched: z = blockIdx.z; per-tensor offset = (z>>3)*hi + (z&7)*lo.
// EPI: 0 +bias | 1 aux + sc*(acc+bias) | 2 aux*sigmoid(acc+bias) | 3 relu
//      4 aux + sc*acc | 5 plain
// Block: 256 thr = 8 warps as 2x(WC). Warp tile: 64 x (BN/WC).
template<int BM, int BN, int WC, int EPI, bool TRANSB>
__global__ void __launch_bounds__(256) gemm_tc(
    const float* __restrict__ A, const float* __restrict__ B,
    const float* __restrict__ bias, const float* __restrict__ aux,
    const float* __restrict__ scale, float alpha,
    float* __restrict__ C,
    int M, int N, int K, int lda, int ldb, int ldc,
    long sAhi, long sAlo, long sBhi, long sBlo, long sChi, long sClo)
{
    constexpr int SA = BM + 8;         // stride ≡ 8 (mod 32) -> conflict-free
    constexpr int SB = BN + 8;
    constexpr int MF = 4;              // 64 rows / 16
    constexpr int NF = BN / WC / 8;
    constexpr int PFA = BM / 64;       // float4 prefetch regs per thread
    constexpr int PFB = BN / 64;

    __shared__ unsigned As[16 * SA];
    __shared__ unsigned Bs[16 * SB];

    const int z = blockIdx.z;
    const float* Ab = A + (size_t)(z >> 3) * sAhi + (size_t)(z & 7) * sAlo
                        + (size_t)blockIdx.y * BM * lda;
    const float* Bb = B + (size_t)(z >> 3) * sBhi + (size_t)(z & 7) * sBlo;
    if (TRANSB) Bb += (size_t)blockIdx.x * BN * ldb;
    else        Bb += (size_t)blockIdx.x * BN;
    float* Cb = C + (size_t)(z >> 3) * sChi + (size_t)(z & 7) * sClo;

    const int t = threadIdx.x;
    const int lane = t & 31, w = t >> 5;
    const int wr = w / WC, wc = w % WC;
    const int r = lane >> 2, cq = lane & 3;
    const int mB = wr * 64, nB = wc * (BN / WC);

    // staging indices
    const int qa = t >> 6;            // k-quad for A (and B when TRANSB)
    const int tm = t & 63;
    const int bRPI = 1024 / BN;       // rows per iter for non-trans B
    const int bkr  = t / (BN / 4);
    const int bn4  = (t & (BN / 4 - 1)) * 4;

    float acc[MF][NF][4];
#pragma unroll
    for (int i = 0; i < MF; i++)
#pragma unroll
        for (int j = 0; j < NF; j++)
#pragma unroll
            for (int e = 0; e < 4; e++) acc[i][j][e] = 0.f;

    float4 pfA[PFA], pfB[PFB];

    auto loadA = [&](int k0) {
#pragma unroll
        for (int i = 0; i < PFA; i++)
            pfA[i] = *(const float4*)(Ab + (size_t)(tm + 64 * i) * lda + k0 + 4 * qa);
    };
    auto loadB = [&](int k0) {
        if (TRANSB) {
#pragma unroll
            for (int i = 0; i < PFB; i++)
                pfB[i] = *(const float4*)(Bb + (size_t)(tm + 64 * i) * ldb + k0 + 4 * qa);
        } else {
#pragma unroll
            for (int i = 0; i < PFB; i++)
                pfB[i] = *(const float4*)(Bb + (size_t)(k0 + bkr + i * bRPI) * ldb + bn4);
        }
    };
    auto storeA = [&]() {
#pragma unroll
        for (int i = 0; i < PFA; i++) {
            int m = tm + 64 * i;
            As[(4 * qa + 0) * SA + m] = f2tf(pfA[i].x);
            As[(4 * qa + 1) * SA + m] = f2tf(pfA[i].y);
            As[(4 * qa + 2) * SA + m] = f2tf(pfA[i].z);
            As[(4 * qa + 3) * SA + m] = f2tf(pfA[i].w);
        }
    };
    auto storeB = [&]() {
        if (TRANSB) {
#pragma unroll
            for (int i = 0; i < PFB; i++) {
                int n = tm + 64 * i;
                Bs[(4 * qa + 0) * SB + n] = f2tf(pfB[i].x);
                Bs[(4 * qa + 1) * SB + n] = f2tf(pfB[i].y);
                Bs[(4 * qa + 2) * SB + n] = f2tf(pfB[i].z);
                Bs[(4 * qa + 3) * SB + n] = f2tf(pfB[i].w);
            }
        } else {
#pragma unroll
            for (int i = 0; i < PFB; i++) {
                uint4 u = { f2tf(pfB[i].x), f2tf(pfB[i].y), f2tf(pfB[i].z), f2tf(pfB[i].w) };
                *(uint4*)&Bs[(bkr + i * bRPI) * SB + bn4] = u;
            }
        }
    };

    const int NC = K >> 4;
    loadA(0); loadB(0);
    for (int c = 0; c < NC; c++) {
        storeA(); storeB();
        __syncthreads();
        if (c + 1 < NC) { loadA((c + 1) << 4); loadB((c + 1) << 4); }
#pragma unroll
        for (int ks = 0; ks < 2; ks++) {
            const int kk = ks * 8;
            unsigned af[MF][4], bf[NF][2];
#pragma unroll
            for (int mf = 0; mf < MF; mf++) {
                int m0 = mB + mf * 16 + r;
                af[mf][0] = As[(kk + cq) * SA + m0];
                af[mf][1] = As[(kk + cq) * SA + m0 + 8];
                af[mf][2] = As[(kk + cq + 4) * SA + m0];
                af[mf][3] = As[(kk + cq + 4) * SA + m0 + 8];
            }
#pragma unroll
            for (int nf = 0; nf < NF; nf++) {
                int n0 = nB + nf * 8 + r;
                bf[nf][0] = Bs[(kk + cq) * SB + n0];
                bf[nf][1] = Bs[(kk + cq + 4) * SB + n0];
            }
#pragma unroll
            for (int mf = 0; mf < MF; mf++)
#pragma unroll
                for (int nf = 0; nf < NF; nf++)
                    mma_tf32(acc[mf][nf], af[mf], bf[nf]);
        }
        __syncthreads();
    }

    // -------- epilogue --------
    float scv = 1.f;
    if constexpr (EPI == 1 || EPI == 4) scv = *scale;
    const int rowBase = blockIdx.y * BM + mB;
    const int colBase = blockIdx.x * BN + nB;
#pragma unroll
    for (int mf = 0; mf < MF; mf++) {
#pragma unroll
        for (int nf = 0; nf < NF; nf++) {
            int n = colBase + nf * 8 + 2 * cq;
#pragma unroll
            for (int h = 0; h < 2; h++) {
                int m = rowBase + mf * 16 + r + 8 * h;
                size_t idx = (size_t)m * ldc + n;
                float v0 = acc[mf][nf][2 * h + 0] * alpha;
                float v1 = acc[mf][nf][2 * h + 1] * alpha;
                if constexpr (EPI == 0) {
                    v0 += bias[n]; v1 += bias[n + 1];
                } else if constexpr (EPI == 1) {
                    v0 = aux[idx]     + scv * (v0 + bias[n]);
                    v1 = aux[idx + 1] + scv * (v1 + bias[n + 1]);
                } else if constexpr (EPI == 2) {
                    v0 = aux[idx]     / (1.f + expf(-(v0 + bias[n])));
                    v1 = aux[idx + 1] / (1.f + expf(-(v1 + bias[n + 1])));
                } else if constexpr (EPI == 3) {
                    v0 = fmaxf(v0, 0.f); v1 = fmaxf(v1, 0.f);
                } else if constexpr (EPI == 4) {
                    v0 = aux[idx]     + scv * v0;
                    v1 = aux[idx + 1] + scv * v1;
                }
                float2 o = { v0, v1 };
                *(float2*)&Cb[idx] = o;
            }
        }
    }
}

// ---------------- in-place row softmax over 1024 ----------------------------
__global__ void __launch_bounds__(256) softmax1024(float* __restrict__ a)
{
    size_t row = blockIdx.x;
    float4* p  = (float4*)(a + row * 1024);
    int t = threadIdx.x;
    float4 v = p[t];
    float m = fmaxf(fmaxf(v.x, v.y), fmaxf(v.z, v.w));
#pragma unroll
    for (int o = 16; o; o >>= 1) m = fmaxf(m, __shfl_xor_sync(~0u, m, o));
    __shared__ float sm[8], ss[8];
    int w = t >> 5, ln = t & 31;
    if (ln == 0) sm[w] = m;
    __syncthreads();
    m = sm[0];
#pragma unroll
    for (int i = 1; i < 8; i++) m = fmaxf(m, sm[i]);
    float e0 = __expf(v.x - m), e1 = __expf(v.y - m);
    float e2 = __expf(v.z - m), e3 = __expf(v.w - m);
    float su = e0 + e1 + e2 + e3;
#pragma unroll
    for (int o = 16; o; o >>= 1) su += __shfl_xor_sync(~0u, su, o);
    if (ln == 0) ss[w] = su;
    __syncthreads();
    float tot = 0.f;
#pragma unroll
    for (int i = 0; i < 8; i++) tot += ss[i];
    float inv = 1.f / tot;
    p[t] = make_float4(e0*inv, e1*inv, e2*inv, e3*inv);
}

// ---------------- mean over L ------------------------------------------------
__global__ void __launch_bounds__(512) col_mean(const float* __restrict__ x,
                                                float* __restrict__ xg)
{
    int b = blockIdx.x, d = threadIdx.x;
    const float* p = x + (size_t)b * LL * DM + d;
    float s = 0.f;
#pragma unroll 8
    for (int t = 0; t < LL; t++) s += p[(size_t)t * DM];
    xg[b*DM + d] = s * (1.0f / (float)LL);
}

// ---------------- kernel-size predictor + masked softmax of taps ------------
__global__ void __launch_bounds__(256) kernel_pred(const float* __restrict__ xg,
                                                   const float* __restrict__ w1,
                                                   const float* __restrict__ b1,
                                                   const float* __restrict__ w2,
                                                   const float* __restrict__ b2,
                                                   const float* __restrict__ tw,
                                                   float* __restrict__ wout,
                                                   int* __restrict__ kout)
{
    int b = blockIdx.x, j = threadIdx.x;
    __shared__ float xs[DM];
    xs[j]       = xg[b*DM + j];
    xs[j + 256] = xg[b*DM + j + 256];
    __syncthreads();
    float hj = b1[j];
#pragma unroll 4
    for (int d = 0; d < DM; d++) hj = fmaf(xs[d], w1[d*256 + j], hj);
    hj = fmaxf(hj, 0.f) * w2[j];
    __shared__ float red[256];
    red[j] = hj;
    __syncthreads();
    for (int s = 128; s; s >>= 1) { if (j < s) red[j] += red[j + s]; __syncthreads(); }
    if (j == 0) {
        float sv = 1.f / (1.f + expf(-(red[0] + b2[0])));
        int kk = (int)rintf(sv * 45.f + 5.f);
        kk = max(5, min(kk, MAXK));
        kout[b] = kk;
        float m = -3.4e38f;
        for (int i = 0; i < kk; i++) m = fmaxf(m, tw[i]);
        float e[MAXK], su = 0.f;
        for (int i = 0; i < kk; i++) { e[i] = expf(tw[i] - m); su += e[i]; }
        float inv = 1.f / su;
        for (int i = 0; i < MAXK; i++) wout[b*MAXK + i] = (i < kk) ? e[i] * inv : 0.f;
    }
}

// ---------------- seasonal = x - depthwise-conv trend (replicate pad) -------
__global__ void __launch_bounds__(512) decomp_kern(const float* __restrict__ x,
                                                   const float* __restrict__ w,
                                                   const int* __restrict__ kk,
                                                   float* __restrict__ out)
{
    int b = blockIdx.y, t = blockIdx.x, d = threadIdx.x;
    int k = kk[b];
    int base = t - (k >> 1);
    const float* wb = w + b*MAXK;
    const float* xb = x + (size_t)b * LL * DM;
    float acc = 0.f;
    for (int i = 0; i < k; i++) {
        int tc = base + i;
        tc = tc < 0 ? 0 : (tc > LL-1 ? LL-1 : tc);
        acc = fmaf(wb[i], xb[(size_t)tc * DM + d], acc);
    }
    size_t o = (size_t)(b*LL + t) * DM + d;
    out[o] = x[o] - acc;
}

// -----------------------------------------------------------------------------
extern "C" void kernel_launch(void* const* d_in, const int* in_sizes, int n_in,
                              void* d_out, int out_size)
{
    const float* x       = (const float*)d_in[0];
    const float* Wq      = (const float*)d_in[1];
    const float* bq      = (const float*)d_in[2];
    const float* Wk      = (const float*)d_in[3];
    const float* bk      = (const float*)d_in[4];
    const float* Wv      = (const float*)d_in[5];
    const float* bv      = (const float*)d_in[6];
    const float* Wo      = (const float*)d_in[7];
    const float* bo      = (const float*)d_in[8];
    const float* gate_w  = (const float*)d_in[9];
    const float* gate_b  = (const float*)d_in[10];
    const float* conv1_w = (const float*)d_in[11];
    const float* conv2_w = (const float*)d_in[12];
    const float* tw1     = (const float*)d_in[13];
    const float* kp1_w1  = (const float*)d_in[14];
    const float* kp1_b1  = (const float*)d_in[15];
    const float* kp1_w2  = (const float*)d_in[16];
    const float* kp1_b2  = (const float*)d_in[17];
    const float* tw2     = (const float*)d_in[18];
    const float* kp2_w1  = (const float*)d_in[19];
    const float* kp2_b1  = (const float*)d_in[20];
    const float* kp2_w2  = (const float*)d_in[21];
    const float* kp2_b2  = (const float*)d_in[22];
    const float* attn_sc = (const float*)d_in[23];
    const float* ffn_sc  = (const float*)d_in[24];

    float* res  = (float*)d_out;                          // [B,L,D]
    float* attn = (float*)d_out + (size_t)BB*LL*DM;       // [B,H,L,L]

    float *q, *k, *v, *t0, *x1, *x2, *gg, *hid, *xg, *wb;
    int* kb;
    cudaGetSymbolAddress((void**)&q,   g_q);
    cudaGetSymbolAddress((void**)&k,   g_k);
    cudaGetSymbolAddress((void**)&v,   g_v);
    cudaGetSymbolAddress((void**)&t0,  g_t0);
    cudaGetSymbolAddress((void**)&x1,  g_x1);
    cudaGetSymbolAddress((void**)&x2,  g_x2);
    cudaGetSymbolAddress((void**)&gg,  g_g);
    cudaGetSymbolAddress((void**)&hid, g_hid);
    cudaGetSymbolAddress((void**)&xg,  g_xg);
    cudaGetSymbolAddress((void**)&wb,  g_w);
    cudaGetSymbolAddress((void**)&kb,  g_kk);

    const dim3 blk(256);
    const long LLDM = (long)LL * DM;
    const long LL2  = (long)LL * LL;

    // QKV projections: [8192,512] = x @ W + b
    gemm_tc<128,128,4,0,false><<<dim3(DM/128, BLN/128, 1), blk>>>(
        x, Wq, bq, nullptr, nullptr, 1.f, q, BLN, DM, DM, DM, DM, DM, 0,0,0,0,0,0);
    gemm_tc<128,128,4,0,false><<<dim3(DM/128, BLN/128, 1), blk>>>(
        x, Wk, bk, nullptr, nullptr, 1.f, k, BLN, DM, DM, DM, DM, DM, 0,0,0,0,0,0);
    gemm_tc<128,128,4,0,false><<<dim3(DM/128, BLN/128, 1), blk>>>(
        x, Wv, bv, nullptr, nullptr, 1.f, v, BLN, DM, DM, DM, DM, DM, 0,0,0,0,0,0);

    // scores: attn[b,h] = (q_bh @ k_bh^T) / 8   (batched over 64 bh)
    gemm_tc<128,128,4,5,true><<<dim3(LL/128, LL/128, BB*HH), blk>>>(
        q, k, nullptr, nullptr, nullptr, 0.125f, attn,
        LL, LL, HD, DM, DM, LL,
        LLDM, HD, LLDM, HD, 8*LL2, LL2);

    softmax1024<<<BB*HH*LL, blk>>>(attn);

    // AV: t0[b,:,h,:] = attn[b,h] @ v[b,:,h,:]  (batched, N=64)
    gemm_tc<128,64,4,5,false><<<dim3(1, LL/128, BB*HH), blk>>>(
        attn, v, nullptr, nullptr, nullptr, 1.f, t0,
        LL, HD, LL, LL, DM, DM,
        8*LL2, LL2, LLDM, HD, LLDM, HD);

    // out proj + residual: x1 = x + attn_scale*(t0@Wo + bo)
    gemm_tc<128,128,4,1,false><<<dim3(DM/128, BLN/128, 1), blk>>>(
        t0, Wo, bo, x, attn_sc, 1.f, x1, BLN, DM, DM, DM, DM, DM, 0,0,0,0,0,0);

    // decomp 1: x2 = seasonal(x1)
    col_mean<<<BB, 512>>>(x1, xg);
    kernel_pred<<<BB, 256>>>(xg, kp1_w1, kp1_b1, kp1_w2, kp1_b2, tw1, wb, kb);
    decomp_kern<<<dim3(LL,BB), 512>>>(x1, wb, kb, x2);

    // FFN: gate -> conv1(relu) -> conv2 + residual
    gemm_tc<128,128,4,2,true><<<dim3(DM/128, BLN/128, 1), blk>>>(
        x2, gate_w, gate_b, x2, nullptr, 1.f, gg, BLN, DM, DM, DM, DM, DM, 0,0,0,0,0,0);
    gemm_tc<128,128,4,3,true><<<dim3(DFF/128, BLN/128, 1), blk>>>(
        gg, conv1_w, nullptr, nullptr, nullptr, 1.f, hid, BLN, DFF, DM, DM, DM, DFF, 0,0,0,0,0,0);
    gemm_tc<128,128,4,4,true><<<dim3(DM/128, BLN/128, 1), blk>>>(
        hid, conv2_w, nullptr, x2, ffn_sc, 1.f, x1, BLN, DM, DFF, DFF, DFF, DM, 0,0,0,0,0,0);

    // decomp 2 -> res (directly into d_out)
    col_mean<<<BB, 512>>>(x1, xg);
    kernel_pred<<<BB, 256>>>(xg, kp2_w1, kp2_b1, kp2_w2, kp2_b2, tw2, wb, kb);
    decomp_kern<<<dim3(LL,BB), 512>>>(x1, wb, kb, res);
}

// round 3
// speedup vs baseline: 2.3822x; 1.4157x over previous
#include <cuda_runtime.h>
#include <math.h>

#define BB 8
#define LL 1024
#define DM 512
#define HH 8
#define HD 64
#define DFF 2048
#define BLN (BB*LL)
#define MAXK 50

// ---------------- scratch (device globals; no allocations allowed) ----------
__device__ float g_q [BLN*DM];
__device__ float g_k [BLN*DM];
__device__ float g_v [BLN*DM];
__device__ float g_t0[BLN*DM];
__device__ float g_x1[BLN*DM];
__device__ float g_x2[BLN*DM];
__device__ float g_g [BLN*DM];
__device__ float g_hid[(size_t)BLN*DFF];
__device__ float g_xg[BB*DM];
__device__ float g_w [BB*MAXK];
__device__ int   g_kk[BB];

// ---------------- helpers ----------------------------------------------------
__device__ __forceinline__ unsigned f2tf(unsigned raw) {
    unsigned r;
    asm("cvt.rna.tf32.f32 %0, %1;" : "=r"(r) : "f"(__uint_as_float(raw)));
    return r;
}

__device__ __forceinline__ void mma_tf32(float c[4], const unsigned a[4], const unsigned b[2]) {
    asm volatile(
        "mma.sync.aligned.m16n8k8.row.col.f32.tf32.tf32.f32 "
        "{%0,%1,%2,%3},{%4,%5,%6,%7},{%8,%9},{%0,%1,%2,%3};"
        : "+f"(c[0]), "+f"(c[1]), "+f"(c[2]), "+f"(c[3])
        : "r"(a[0]), "r"(a[1]), "r"(a[2]), "r"(a[3]), "r"(b[0]), "r"(b[1]));
}

__device__ __forceinline__ void cpa16(void* dst, const void* src) {
    unsigned d = (unsigned)__cvta_generic_to_shared(dst);
    asm volatile("cp.async.cg.shared.global [%0], [%1], 16;" :: "r"(d), "l"(src));
}
__device__ __forceinline__ void cpa_commit() {
    asm volatile("cp.async.commit_group;");
}
template<int N>
__device__ __forceinline__ void cpa_wait() {
    asm volatile("cp.async.wait_group %0;" :: "n"(N));
}

// ---------------- tf32 tensor-core GEMM, cp.async 3-stage pipeline ----------
// C[M,N] = epi(alpha * A[M,K] @ B) ; TRANSB ? B stored [N,K] : [K,N]
// Batched: z = blockIdx.z; per-tensor offset = (z>>3)*hi + (z&7)*lo.
// EPI: 0 +bias | 1 aux+sc*(acc+bias) | 2 aux*sigmoid(acc+bias) | 3 relu
//      4 aux+sc*acc | 5 plain
// 256 thr = 8 warps (2 rows x 4 cols). Warp tile 64 x (BN/4).
template<int BM, int BN, int EPI, bool TRANSB>
__global__ void __launch_bounds__(256, 2) gemm_cp(
    const float* __restrict__ A, const float* __restrict__ B,
    const float* __restrict__ bias, const float* __restrict__ aux,
    const float* __restrict__ scale, float alpha,
    float* __restrict__ C,
    int M, int N, int K, int lda, int ldb, int ldc,
    long sAhi, long sAlo, long sBhi, long sBlo, long sChi, long sClo)
{
    constexpr int SK   = 20;                    // row stride (words) for [m][k]/[n][k]
    constexpr int SBnt = BN + 8;                // k-row stride for [k][n]
    constexpr int ASTG = BM * SK;               // words per stage
    constexpr int BSTG = TRANSB ? BN * SK : 16 * SBnt;
    constexpr int NF   = BN / 32;               // mma n-frags per warp
    constexpr int NA   = BM * 4 / 256;          // A 16B chunks per thread
    constexpr int NBt  = BN * 4 / 256 ? BN * 4 / 256 : 1;
    constexpr int NBn  = 16 * (BN / 4) / 256 ? 16 * (BN / 4) / 256 : 1;

    extern __shared__ unsigned smem[];
    unsigned* As = smem;                        // 3*ASTG
    unsigned* Bs = smem + 3 * ASTG;             // 3*BSTG

    const int z = blockIdx.z;
    const float* Ab = A + (size_t)(z >> 3) * sAhi + (size_t)(z & 7) * sAlo
                        + (size_t)blockIdx.y * BM * lda;
    const float* Bb = B + (size_t)(z >> 3) * sBhi + (size_t)(z & 7) * sBlo;
    if (TRANSB) Bb += (size_t)blockIdx.x * BN * ldb;
    else        Bb += (size_t)blockIdx.x * BN;
    float* Cb = C + (size_t)(z >> 3) * sChi + (size_t)(z & 7) * sClo;

    const int t = threadIdx.x;
    const int lane = t & 31, w = t >> 5;
    const int wr = w >> 2, wc = w & 3;
    const int r = lane >> 2, cq = lane & 3;
    const int mB = wr * 64, nB = wc * (BN / 4);

    const int NC = K >> 4;

    auto issue = [&](int s) {
        if (s < NC) {
            const int k0 = s << 4;
            unsigned* Ad = As + (s % 3) * ASTG;
#pragma unroll
            for (int i = 0; i < NA; i++) {
                int cid = t + i * 256;
                int row = cid >> 2, j = (cid & 3) * 4;
                cpa16(Ad + row * SK + j, Ab + (size_t)row * lda + k0 + j);
            }
            unsigned* Bd = Bs + (s % 3) * BSTG;
            if (TRANSB) {
#pragma unroll
                for (int i = 0; i < NBt; i++) {
                    int cid = t + i * 256;
                    int row = cid >> 2, j = (cid & 3) * 4;
                    cpa16(Bd + row * SK + j, Bb + (size_t)row * ldb + k0 + j);
                }
            } else {
#pragma unroll
                for (int i = 0; i < NBn; i++) {
                    int cid = t + i * 256;
                    int kr = cid / (BN / 4), n4 = (cid % (BN / 4)) * 4;
                    cpa16(Bd + kr * SBnt + n4, Bb + (size_t)(k0 + kr) * ldb + n4);
                }
            }
        }
        cpa_commit();
    };

    float acc[4][NF][4];
#pragma unroll
    for (int i = 0; i < 4; i++)
#pragma unroll
        for (int j = 0; j < NF; j++)
#pragma unroll
            for (int e = 0; e < 4; e++) acc[i][j][e] = 0.f;

    issue(0);
    issue(1);

    for (int c = 0; c < NC; c++) {
        cpa_wait<1>();
        __syncthreads();
        const unsigned* Ac = As + (c % 3) * ASTG;
        const unsigned* Bc = Bs + (c % 3) * BSTG;
#pragma unroll
        for (int ks = 0; ks < 2; ks++) {
            const int kk = ks * 8;
            unsigned af[4][4], bf[NF][2];
#pragma unroll
            for (int mf = 0; mf < 4; mf++) {
                const unsigned* ap = Ac + (mB + mf * 16 + r) * SK + kk + cq;
                af[mf][0] = f2tf(ap[0]);
                af[mf][1] = f2tf(ap[8 * SK]);
                af[mf][2] = f2tf(ap[4]);
                af[mf][3] = f2tf(ap[8 * SK + 4]);
            }
#pragma unroll
            for (int nf = 0; nf < NF; nf++) {
                if (TRANSB) {
                    const unsigned* bp = Bc + (nB + nf * 8 + r) * SK + kk + cq;
                    bf[nf][0] = f2tf(bp[0]);
                    bf[nf][1] = f2tf(bp[4]);
                } else {
                    const unsigned* bp = Bc + (kk + cq) * SBnt + nB + nf * 8 + r;
                    bf[nf][0] = f2tf(bp[0]);
                    bf[nf][1] = f2tf(bp[4 * SBnt]);
                }
            }
#pragma unroll
            for (int mf = 0; mf < 4; mf++)
#pragma unroll
                for (int nf = 0; nf < NF; nf++)
                    mma_tf32(acc[mf][nf], af[mf], bf[nf]);
        }
        __syncthreads();
        issue(c + 2);
    }

    // -------- epilogue --------
    float scv = 1.f;
    if constexpr (EPI == 1 || EPI == 4) scv = *scale;
    const int rowBase = blockIdx.y * BM + mB;
    const int colBase = blockIdx.x * BN + nB;
#pragma unroll
    for (int mf = 0; mf < 4; mf++) {
#pragma unroll
        for (int nf = 0; nf < NF; nf++) {
            int n = colBase + nf * 8 + 2 * cq;
#pragma unroll
            for (int h = 0; h < 2; h++) {
                int m = rowBase + mf * 16 + r + 8 * h;
                size_t idx = (size_t)m * ldc + n;
                float v0 = acc[mf][nf][2 * h + 0] * alpha;
                float v1 = acc[mf][nf][2 * h + 1] * alpha;
                if constexpr (EPI == 0) {
                    v0 += bias[n]; v1 += bias[n + 1];
                } else if constexpr (EPI == 1) {
                    v0 = aux[idx]     + scv * (v0 + bias[n]);
                    v1 = aux[idx + 1] + scv * (v1 + bias[n + 1]);
                } else if constexpr (EPI == 2) {
                    v0 = aux[idx]     / (1.f + expf(-(v0 + bias[n])));
                    v1 = aux[idx + 1] / (1.f + expf(-(v1 + bias[n + 1])));
                } else if constexpr (EPI == 3) {
                    v0 = fmaxf(v0, 0.f); v1 = fmaxf(v1, 0.f);
                } else if constexpr (EPI == 4) {
                    v0 = aux[idx]     + scv * v0;
                    v1 = aux[idx + 1] + scv * v1;
                }
                float2 o = { v0, v1 };
                *(float2*)&Cb[idx] = o;
            }
        }
    }
}

// ---------------- in-place row softmax over 1024 ----------------------------
__global__ void __launch_bounds__(256) softmax1024(float* __restrict__ a)
{
    size_t row = blockIdx.x;
    float4* p  = (float4*)(a + row * 1024);
    int t = threadIdx.x;
    float4 v = p[t];
    float m = fmaxf(fmaxf(v.x, v.y), fmaxf(v.z, v.w));
#pragma unroll
    for (int o = 16; o; o >>= 1) m = fmaxf(m, __shfl_xor_sync(~0u, m, o));
    __shared__ float sm[8], ss[8];
    int w = t >> 5, ln = t & 31;
    if (ln == 0) sm[w] = m;
    __syncthreads();
    m = sm[0];
#pragma unroll
    for (int i = 1; i < 8; i++) m = fmaxf(m, sm[i]);
    float e0 = __expf(v.x - m), e1 = __expf(v.y - m);
    float e2 = __expf(v.z - m), e3 = __expf(v.w - m);
    float su = e0 + e1 + e2 + e3;
#pragma unroll
    for (int o = 16; o; o >>= 1) su += __shfl_xor_sync(~0u, su, o);
    if (ln == 0) ss[w] = su;
    __syncthreads();
    float tot = 0.f;
#pragma unroll
    for (int i = 0; i < 8; i++) tot += ss[i];
    float inv = 1.f / tot;
    p[t] = make_float4(e0*inv, e1*inv, e2*inv, e3*inv);
}

// ---------------- mean over L ------------------------------------------------
__global__ void __launch_bounds__(512) col_mean(const float* __restrict__ x,
                                                float* __restrict__ xg)
{
    int b = blockIdx.x, d = threadIdx.x;
    const float* p = x + (size_t)b * LL * DM + d;
    float s = 0.f;
#pragma unroll 8
    for (int t = 0; t < LL; t++) s += p[(size_t)t * DM];
    xg[b*DM + d] = s * (1.0f / (float)LL);
}

// ---------------- kernel-size predictor + masked softmax of taps ------------
__global__ void __launch_bounds__(256) kernel_pred(const float* __restrict__ xg,
                                                   const float* __restrict__ w1,
                                                   const float* __restrict__ b1,
                                                   const float* __restrict__ w2,
                                                   const float* __restrict__ b2,
                                                   const float* __restrict__ tw,
                                                   float* __restrict__ wout,
                                                   int* __restrict__ kout)
{
    int b = blockIdx.x, j = threadIdx.x;
    __shared__ float xs[DM];
    xs[j]       = xg[b*DM + j];
    xs[j + 256] = xg[b*DM + j + 256];
    __syncthreads();
    float hj = b1[j];
#pragma unroll 4
    for (int d = 0; d < DM; d++) hj = fmaf(xs[d], w1[d*256 + j], hj);
    hj = fmaxf(hj, 0.f) * w2[j];
    __shared__ float red[256];
    red[j] = hj;
    __syncthreads();
    for (int s = 128; s; s >>= 1) { if (j < s) red[j] += red[j + s]; __syncthreads(); }
    if (j == 0) {
        float sv = 1.f / (1.f + expf(-(red[0] + b2[0])));
        int kk = (int)rintf(sv * 45.f + 5.f);
        kk = max(5, min(kk, MAXK));
        kout[b] = kk;
        float m = -3.4e38f;
        for (int i = 0; i < kk; i++) m = fmaxf(m, tw[i]);
        float e[MAXK], su = 0.f;
        for (int i = 0; i < kk; i++) { e[i] = expf(tw[i] - m); su += e[i]; }
        float inv = 1.f / su;
        for (int i = 0; i < MAXK; i++) wout[b*MAXK + i] = (i < kk) ? e[i] * inv : 0.f;
    }
}

// ---------------- seasonal = x - depthwise-conv trend (replicate pad) -------
__global__ void __launch_bounds__(512) decomp_kern(const float* __restrict__ x,
                                                   const float* __restrict__ w,
                                                   const int* __restrict__ kk,
                                                   float* __restrict__ out)
{
    int b = blockIdx.y, t = blockIdx.x, d = threadIdx.x;
    int k = kk[b];
    int base = t - (k >> 1);
    const float* wb = w + b*MAXK;
    const float* xb = x + (size_t)b * LL * DM;
    float acc = 0.f;
    for (int i = 0; i < k; i++) {
        int tc = base + i;
        tc = tc < 0 ? 0 : (tc > LL-1 ? LL-1 : tc);
        acc = fmaf(wb[i], xb[(size_t)tc * DM + d], acc);
    }
    size_t o = (size_t)(b*LL + t) * DM + d;
    out[o] = x[o] - acc;
}

// -----------------------------------------------------------------------------
static inline int smem_size(int BM, int BN, bool transB) {
    int astg = BM * 20;
    int bstg = transB ? BN * 20 : 16 * (BN + 8);
    return 3 * (astg + bstg) * 4;
}

extern "C" void kernel_launch(void* const* d_in, const int* in_sizes, int n_in,
                              void* d_out, int out_size)
{
    const float* x       = (const float*)d_in[0];
    const float* Wq      = (const float*)d_in[1];
    const float* bq      = (const float*)d_in[2];
    const float* Wk      = (const float*)d_in[3];
    const float* bk      = (const float*)d_in[4];
    const float* Wv      = (const float*)d_in[5];
    const float* bv      = (const float*)d_in[6];
    const float* Wo      = (const float*)d_in[7];
    const float* bo      = (const float*)d_in[8];
    const float* gate_w  = (const float*)d_in[9];
    const float* gate_b  = (const float*)d_in[10];
    const float* conv1_w = (const float*)d_in[11];
    const float* conv2_w = (const float*)d_in[12];
    const float* tw1     = (const float*)d_in[13];
    const float* kp1_w1  = (const float*)d_in[14];
    const float* kp1_b1  = (const float*)d_in[15];
    const float* kp1_w2  = (const float*)d_in[16];
    const float* kp1_b2  = (const float*)d_in[17];
    const float* tw2     = (const float*)d_in[18];
    const float* kp2_w1  = (const float*)d_in[19];
    const float* kp2_b1  = (const float*)d_in[20];
    const float* kp2_w2  = (const float*)d_in[21];
    const float* kp2_b2  = (const float*)d_in[22];
    const float* attn_sc = (const float*)d_in[23];
    const float* ffn_sc  = (const float*)d_in[24];

    float* res  = (float*)d_out;                          // [B,L,D]
    float* attn = (float*)d_out + (size_t)BB*LL*DM;       // [B,H,L,L]

    float *q, *k, *v, *t0, *x1, *x2, *gg, *hid, *xg, *wb;
    int* kb;
    cudaGetSymbolAddress((void**)&q,   g_q);
    cudaGetSymbolAddress((void**)&k,   g_k);
    cudaGetSymbolAddress((void**)&v,   g_v);
    cudaGetSymbolAddress((void**)&t0,  g_t0);
    cudaGetSymbolAddress((void**)&x1,  g_x1);
    cudaGetSymbolAddress((void**)&x2,  g_x2);
    cudaGetSymbolAddress((void**)&gg,  g_g);
    cudaGetSymbolAddress((void**)&hid, g_hid);
    cudaGetSymbolAddress((void**)&xg,  g_xg);
    cudaGetSymbolAddress((void**)&wb,  g_w);
    cudaGetSymbolAddress((void**)&kb,  g_kk);

    const int szNT  = smem_size(128, 128, false);  // 56832
    const int szT   = smem_size(128, 128, true);   // 61440
    const int szAV  = smem_size(128,  64, false);  // 44544

    cudaFuncSetAttribute(gemm_cp<128,128,0,false>, cudaFuncAttributeMaxDynamicSharedMemorySize, szNT);
    cudaFuncSetAttribute(gemm_cp<128,128,5,true >, cudaFuncAttributeMaxDynamicSharedMemorySize, szT);
    cudaFuncSetAttribute(gemm_cp<128, 64,5,false>, cudaFuncAttributeMaxDynamicSharedMemorySize, szAV);
    cudaFuncSetAttribute(gemm_cp<128,128,1,false>, cudaFuncAttributeMaxDynamicSharedMemorySize, szNT);
    cudaFuncSetAttribute(gemm_cp<128,128,2,true >, cudaFuncAttributeMaxDynamicSharedMemorySize, szT);
    cudaFuncSetAttribute(gemm_cp<128,128,3,true >, cudaFuncAttributeMaxDynamicSharedMemorySize, szT);
    cudaFuncSetAttribute(gemm_cp<128,128,4,true >, cudaFuncAttributeMaxDynamicSharedMemorySize, szT);

    const dim3 blk(256);
    const long LLDM = (long)LL * DM;
    const long LL2  = (long)LL * LL;

    // QKV projections
    gemm_cp<128,128,0,false><<<dim3(DM/128, BLN/128, 1), blk, szNT>>>(
        x, Wq, bq, nullptr, nullptr, 1.f, q, BLN, DM, DM, DM, DM, DM, 0,0,0,0,0,0);
    gemm_cp<128,128,0,false><<<dim3(DM/128, BLN/128, 1), blk, szNT>>>(
        x, Wk, bk, nullptr, nullptr, 1.f, k, BLN, DM, DM, DM, DM, DM, 0,0,0,0,0,0);
    gemm_cp<128,128,0,false><<<dim3(DM/128, BLN/128, 1), blk, szNT>>>(
        x, Wv, bv, nullptr, nullptr, 1.f, v, BLN, DM, DM, DM, DM, DM, 0,0,0,0,0,0);

    // scores: attn[b,h] = (q_bh @ k_bh^T) / 8
    gemm_cp<128,128,5,true><<<dim3(LL/128, LL/128, BB*HH), blk, szT>>>(
        q, k, nullptr, nullptr, nullptr, 0.125f, attn,
        LL, LL, HD, DM, DM, LL,
        LLDM, HD, LLDM, HD, 8*LL2, LL2);

    softmax1024<<<BB*HH*LL, blk>>>(attn);

    // AV: t0[b,:,h,:] = attn[b,h] @ v[b,:,h,:]
    gemm_cp<128,64,5,false><<<dim3(1, LL/128, BB*HH), blk, szAV>>>(
        attn, v, nullptr, nullptr, nullptr, 1.f, t0,
        LL, HD, LL, LL, DM, DM,
        8*LL2, LL2, LLDM, HD, LLDM, HD);

    // out proj + residual
    gemm_cp<128,128,1,false><<<dim3(DM/128, BLN/128, 1), blk, szNT>>>(
        t0, Wo, bo, x, attn_sc, 1.f, x1, BLN, DM, DM, DM, DM, DM, 0,0,0,0,0,0);

    // decomp 1
    col_mean<<<BB, 512>>>(x1, xg);
    kernel_pred<<<BB, 256>>>(xg, kp1_w1, kp1_b1, kp1_w2, kp1_b2, tw1, wb, kb);
    decomp_kern<<<dim3(LL,BB), 512>>>(x1, wb, kb, x2);

    // FFN
    gemm_cp<128,128,2,true><<<dim3(DM/128, BLN/128, 1), blk, szT>>>(
        x2, gate_w, gate_b, x2, nullptr, 1.f, gg, BLN, DM, DM, DM, DM, DM, 0,0,0,0,0,0);
    gemm_cp<128,128,3,true><<<dim3(DFF/128, BLN/128, 1), blk, szT>>>(
        gg, conv1_w, nullptr, nullptr, nullptr, 1.f, hid, BLN, DFF, DM, DM, DM, DFF, 0,0,0,0,0,0);
    gemm_cp<128,128,4,true><<<dim3(DM/128, BLN/128, 1), blk, szT>>>(
        hid, conv2_w, nullptr, x2, ffn_sc, 1.f, x1, BLN, DM, DFF, DFF, DFF, DM, 0,0,0,0,0,0);

    // decomp 2 -> res
    col_mean<<<BB, 512>>>(x1, xg);
    kernel_pred<<<BB, 256>>>(xg, kp2_w1, kp2_b1, kp2_w2, kp2_b2, tw2, wb, kb);
    decomp_kern<<<dim3(LL,BB), 512>>>(x1, wb, kb, res);
}

// round 4
// speedup vs baseline: 2.4782x; 1.0403x over previous
#include <cuda_runtime.h>
#include <math.h>

#define BB 8
#define LL 1024
#define DM 512
#define HH 8
#define HD 64
#define DFF 2048
#define BLN (BB*LL)
#define MAXK 50

// ---------------- scratch (device globals; no allocations allowed) ----------
__device__ float g_q [BLN*DM];
__device__ float g_k [BLN*DM];
__device__ float g_v [BLN*DM];
__device__ float g_t0[BLN*DM];
__device__ float g_x1[BLN*DM];
__device__ float g_x2[BLN*DM];
__device__ float g_g [BLN*DM];
__device__ float g_hid[(size_t)BLN*DFF];
__device__ float g_xtf[BLN*DM];
__device__ float g_wts[5*DM*DM + 2*DM*DFF];
__device__ float g_xg[BB*DM];
__device__ float g_w [BB*MAXK];
__device__ int   g_kk[BB];

// ---------------- helpers ----------------------------------------------------
__device__ __forceinline__ unsigned f2tf(unsigned raw) {
    unsigned r;
    asm("cvt.rna.tf32.f32 %0, %1;" : "=r"(r) : "f"(__uint_as_float(raw)));
    return r;
}
__device__ __forceinline__ float f2tff(float x) {
    unsigned r;
    asm("cvt.rna.tf32.f32 %0, %1;" : "=r"(r) : "f"(x));
    return __uint_as_float(r);
}

__device__ __forceinline__ void mma_tf32(float c[4], const unsigned a[4], const unsigned b[2]) {
    asm volatile(
        "mma.sync.aligned.m16n8k8.row.col.f32.tf32.tf32.f32 "
        "{%0,%1,%2,%3},{%4,%5,%6,%7},{%8,%9},{%0,%1,%2,%3};"
        : "+f"(c[0]), "+f"(c[1]), "+f"(c[2]), "+f"(c[3])
        : "r"(a[0]), "r"(a[1]), "r"(a[2]), "r"(a[3]), "r"(b[0]), "r"(b[1]));
}

__device__ __forceinline__ void cpa16(void* dst, const void* src) {
    unsigned d = (unsigned)__cvta_generic_to_shared(dst);
    asm volatile("cp.async.cg.shared.global [%0], [%1], 16;" :: "r"(d), "l"(src));
}
__device__ __forceinline__ void cpa_commit() {
    asm volatile("cp.async.commit_group;");
}
template<int N>
__device__ __forceinline__ void cpa_wait() {
    asm volatile("cp.async.wait_group %0;" :: "n"(N));
}

// ---------------- elementwise tf32 pre-round ---------------------------------
__global__ void __launch_bounds__(256) cvt_tf32(const float4* __restrict__ src,
                                                float4* __restrict__ dst, int n4)
{
    int i = blockIdx.x * 256 + threadIdx.x;
    if (i < n4) {
        float4 v = src[i];
        v.x = f2tff(v.x); v.y = f2tff(v.y); v.z = f2tff(v.z); v.w = f2tff(v.w);
        dst[i] = v;
    }
}

// ---------------- tf32 tensor-core GEMM, cp.async 4-stage pipeline ----------
// C[M,N] = epi(alpha * A[M,K] @ B) ; TRANSB ? B stored [N,K] : [K,N]
// CVA/CVB: apply tf32 rounding at fragment load (operand not pre-rounded).
// ROUT: round output to tf32 bits (for tensors that only feed later GEMMs).
// EPI: 0 +bias | 1 aux+sc*(acc+bias) | 2 aux*sigmoid(acc+bias) | 3 relu
//      4 aux+sc*acc | 5 plain
template<int BM, int BN, int EPI, bool TRANSB, bool CVA, bool CVB, bool ROUT>
__global__ void __launch_bounds__(256, 2) gemm_cp(
    const float* __restrict__ A, const float* __restrict__ B,
    const float* __restrict__ bias, const float* __restrict__ aux,
    const float* __restrict__ scale, float alpha,
    float* __restrict__ C,
    int M, int N, int K, int lda, int ldb, int ldc,
    long sAhi, long sAlo, long sBhi, long sBlo, long sChi, long sClo)
{
    constexpr int SK   = 20;
    constexpr int SBnt = BN + 8;
    constexpr int ASTG = BM * SK;
    constexpr int BSTG = TRANSB ? BN * SK : 16 * SBnt;
    constexpr int NF   = BN / 32;
    constexpr int NA   = BM * 4 / 256;
    constexpr int NBt  = BN * 4 / 256 ? BN * 4 / 256 : 1;
    constexpr int NBn  = 16 * (BN / 4) / 256 ? 16 * (BN / 4) / 256 : 1;

    extern __shared__ unsigned smem[];
    unsigned* As = smem;                  // 4*ASTG
    unsigned* Bs = smem + 4 * ASTG;       // 4*BSTG

    const int z = blockIdx.z;
    const float* Ab = A + (size_t)(z >> 3) * sAhi + (size_t)(z & 7) * sAlo
                        + (size_t)blockIdx.y * BM * lda;
    const float* Bb = B + (size_t)(z >> 3) * sBhi + (size_t)(z & 7) * sBlo;
    if (TRANSB) Bb += (size_t)blockIdx.x * BN * ldb;
    else        Bb += (size_t)blockIdx.x * BN;
    float* Cb = C + (size_t)(z >> 3) * sChi + (size_t)(z & 7) * sClo;

    const int t = threadIdx.x;
    const int lane = t & 31, w = t >> 5;
    const int wr = w >> 2, wc = w & 3;
    const int r = lane >> 2, cq = lane & 3;
    const int mB = wr * 64, nB = wc * (BN / 4);

    const int NC = K >> 4;

    auto issue = [&](int s) {
        if (s < NC) {
            const int k0 = s << 4;
            unsigned* Ad = As + (s & 3) * ASTG;
#pragma unroll
            for (int i = 0; i < NA; i++) {
                int cid = t + i * 256;
                int row = cid >> 2, j = (cid & 3) * 4;
                cpa16(Ad + row * SK + j, Ab + (size_t)row * lda + k0 + j);
            }
            unsigned* Bd = Bs + (s & 3) * BSTG;
            if (TRANSB) {
#pragma unroll
                for (int i = 0; i < NBt; i++) {
                    int cid = t + i * 256;
                    int row = cid >> 2, j = (cid & 3) * 4;
                    cpa16(Bd + row * SK + j, Bb + (size_t)row * ldb + k0 + j);
                }
            } else {
#pragma unroll
                for (int i = 0; i < NBn; i++) {
                    int cid = t + i * 256;
                    int kr = cid / (BN / 4), n4 = (cid % (BN / 4)) * 4;
                    cpa16(Bd + kr * SBnt + n4, Bb + (size_t)(k0 + kr) * ldb + n4);
                }
            }
        }
        cpa_commit();
    };

    float acc[4][NF][4];
#pragma unroll
    for (int i = 0; i < 4; i++)
#pragma unroll
        for (int j = 0; j < NF; j++)
#pragma unroll
            for (int e = 0; e < 4; e++) acc[i][j][e] = 0.f;

    issue(0); issue(1); issue(2);

    for (int c = 0; c < NC; c++) {
        cpa_wait<2>();
        __syncthreads();
        const unsigned* Ac = As + (c & 3) * ASTG;
        const unsigned* Bc = Bs + (c & 3) * BSTG;
#pragma unroll
        for (int ks = 0; ks < 2; ks++) {
            const int kk = ks * 8;
            unsigned af[4][4], bf[NF][2];
#pragma unroll
            for (int mf = 0; mf < 4; mf++) {
                const unsigned* ap = Ac + (mB + mf * 16 + r) * SK + kk + cq;
                unsigned a0 = ap[0], a1 = ap[8 * SK], a2 = ap[4], a3 = ap[8 * SK + 4];
                af[mf][0] = CVA ? f2tf(a0) : a0;
                af[mf][1] = CVA ? f2tf(a1) : a1;
                af[mf][2] = CVA ? f2tf(a2) : a2;
                af[mf][3] = CVA ? f2tf(a3) : a3;
            }
#pragma unroll
            for (int nf = 0; nf < NF; nf++) {
                unsigned b0, b1;
                if (TRANSB) {
                    const unsigned* bp = Bc + (nB + nf * 8 + r) * SK + kk + cq;
                    b0 = bp[0]; b1 = bp[4];
                } else {
                    const unsigned* bp = Bc + (kk + cq) * SBnt + nB + nf * 8 + r;
                    b0 = bp[0]; b1 = bp[4 * SBnt];
                }
                bf[nf][0] = CVB ? f2tf(b0) : b0;
                bf[nf][1] = CVB ? f2tf(b1) : b1;
            }
#pragma unroll
            for (int mf = 0; mf < 4; mf++)
#pragma unroll
                for (int nf = 0; nf < NF; nf++)
                    mma_tf32(acc[mf][nf], af[mf], bf[nf]);
        }
        issue(c + 3);
    }

    // -------- epilogue --------
    float scv = 1.f;
    if constexpr (EPI == 1 || EPI == 4) scv = *scale;
    const int rowBase = blockIdx.y * BM + mB;
    const int colBase = blockIdx.x * BN + nB;
#pragma unroll
    for (int mf = 0; mf < 4; mf++) {
#pragma unroll
        for (int nf = 0; nf < NF; nf++) {
            int n = colBase + nf * 8 + 2 * cq;
#pragma unroll
            for (int h = 0; h < 2; h++) {
                int m = rowBase + mf * 16 + r + 8 * h;
                size_t idx = (size_t)m * ldc + n;
                float v0 = acc[mf][nf][2 * h + 0] * alpha;
                float v1 = acc[mf][nf][2 * h + 1] * alpha;
                if constexpr (EPI == 0) {
                    v0 += bias[n]; v1 += bias[n + 1];
                } else if constexpr (EPI == 1) {
                    v0 = aux[idx]     + scv * (v0 + bias[n]);
                    v1 = aux[idx + 1] + scv * (v1 + bias[n + 1]);
                } else if constexpr (EPI == 2) {
                    v0 = aux[idx]     / (1.f + expf(-(v0 + bias[n])));
                    v1 = aux[idx + 1] / (1.f + expf(-(v1 + bias[n + 1])));
                } else if constexpr (EPI == 3) {
                    v0 = fmaxf(v0, 0.f); v1 = fmaxf(v1, 0.f);
                } else if constexpr (EPI == 4) {
                    v0 = aux[idx]     + scv * v0;
                    v1 = aux[idx + 1] + scv * v1;
                }
                if constexpr (ROUT) { v0 = f2tff(v0); v1 = f2tff(v1); }
                float2 o = { v0, v1 };
                *(float2*)&Cb[idx] = o;
            }
        }
    }
}

// ---------------- in-place row softmax over 1024 ----------------------------
__global__ void __launch_bounds__(256) softmax1024(float* __restrict__ a)
{
    size_t row = blockIdx.x;
    float4* p  = (float4*)(a + row * 1024);
    int t = threadIdx.x;
    float4 v = p[t];
    float m = fmaxf(fmaxf(v.x, v.y), fmaxf(v.z, v.w));
#pragma unroll
    for (int o = 16; o; o >>= 1) m = fmaxf(m, __shfl_xor_sync(~0u, m, o));
    __shared__ float sm[8], ss[8];
    int w = t >> 5, ln = t & 31;
    if (ln == 0) sm[w] = m;
    __syncthreads();
    m = sm[0];
#pragma unroll
    for (int i = 1; i < 8; i++) m = fmaxf(m, sm[i]);
    float e0 = __expf(v.x - m), e1 = __expf(v.y - m);
    float e2 = __expf(v.z - m), e3 = __expf(v.w - m);
    float su = e0 + e1 + e2 + e3;
#pragma unroll
    for (int o = 16; o; o >>= 1) su += __shfl_xor_sync(~0u, su, o);
    if (ln == 0) ss[w] = su;
    __syncthreads();
    float tot = 0.f;
#pragma unroll
    for (int i = 0; i < 8; i++) tot += ss[i];
    float inv = 1.f / tot;
    p[t] = make_float4(e0*inv, e1*inv, e2*inv, e3*inv);
}

// ---------------- mean over L ------------------------------------------------
__global__ void __launch_bounds__(512) col_mean(const float* __restrict__ x,
                                                float* __restrict__ xg)
{
    int b = blockIdx.x, d = threadIdx.x;
    const float* p = x + (size_t)b * LL * DM + d;
    float s = 0.f;
#pragma unroll 8
    for (int t = 0; t < LL; t++) s += p[(size_t)t * DM];
    xg[b*DM + d] = s * (1.0f / (float)LL);
}

// ---------------- kernel-size predictor + masked softmax of taps ------------
__global__ void __launch_bounds__(256) kernel_pred(const float* __restrict__ xg,
                                                   const float* __restrict__ w1,
                                                   const float* __restrict__ b1,
                                                   const float* __restrict__ w2,
                                                   const float* __restrict__ b2,
                                                   const float* __restrict__ tw,
                                                   float* __restrict__ wout,
                                                   int* __restrict__ kout)
{
    int b = blockIdx.x, j = threadIdx.x;
    __shared__ float xs[DM];
    xs[j]       = xg[b*DM + j];
    xs[j + 256] = xg[b*DM + j + 256];
    __syncthreads();
    float hj = b1[j];
#pragma unroll 4
    for (int d = 0; d < DM; d++) hj = fmaf(xs[d], w1[d*256 + j], hj);
    hj = fmaxf(hj, 0.f) * w2[j];
    __shared__ float red[256];
    red[j] = hj;
    __syncthreads();
    for (int s = 128; s; s >>= 1) { if (j < s) red[j] += red[j + s]; __syncthreads(); }
    if (j == 0) {
        float sv = 1.f / (1.f + expf(-(red[0] + b2[0])));
        int kk = (int)rintf(sv * 45.f + 5.f);
        kk = max(5, min(kk, MAXK));
        kout[b] = kk;
        float m = -3.4e38f;
        for (int i = 0; i < kk; i++) m = fmaxf(m, tw[i]);
        float e[MAXK], su = 0.f;
        for (int i = 0; i < kk; i++) { e[i] = expf(tw[i] - m); su += e[i]; }
        float inv = 1.f / su;
        for (int i = 0; i < MAXK; i++) wout[b*MAXK + i] = (i < kk) ? e[i] * inv : 0.f;
    }
}

// ---------------- seasonal = x - depthwise-conv trend (replicate pad) -------
__global__ void __launch_bounds__(512) decomp_kern(const float* __restrict__ x,
                                                   const float* __restrict__ w,
                                                   const int* __restrict__ kk,
                                                   float* __restrict__ out)
{
    int b = blockIdx.y, t = blockIdx.x, d = threadIdx.x;
    int k = kk[b];
    int base = t - (k >> 1);
    const float* wb = w + b*MAXK;
    const float* xb = x + (size_t)b * LL * DM;
    float acc = 0.f;
    for (int i = 0; i < k; i++) {
        int tc = base + i;
        tc = tc < 0 ? 0 : (tc > LL-1 ? LL-1 : tc);
        acc = fmaf(wb[i], xb[(size_t)tc * DM + d], acc);
    }
    size_t o = (size_t)(b*LL + t) * DM + d;
    out[o] = x[o] - acc;
}

// -----------------------------------------------------------------------------
static inline int smem_size(int BM, int BN, bool transB) {
    int astg = BM * 20;
    int bstg = transB ? BN * 20 : 16 * (BN + 8);
    return 4 * (astg + bstg) * 4;
}

extern "C" void kernel_launch(void* const* d_in, const int* in_sizes, int n_in,
                              void* d_out, int out_size)
{
    const float* x       = (const float*)d_in[0];
    const float* Wq      = (const float*)d_in[1];
    const float* bq      = (const float*)d_in[2];
    const float* Wk      = (const float*)d_in[3];
    const float* bk      = (const float*)d_in[4];
    const float* Wv      = (const float*)d_in[5];
    const float* bv      = (const float*)d_in[6];
    const float* Wo      = (const float*)d_in[7];
    const float* bo      = (const float*)d_in[8];
    const float* gate_w  = (const float*)d_in[9];
    const float* gate_b  = (const float*)d_in[10];
    const float* conv1_w = (const float*)d_in[11];
    const float* conv2_w = (const float*)d_in[12];
    const float* tw1     = (const float*)d_in[13];
    const float* kp1_w1  = (const float*)d_in[14];
    const float* kp1_b1  = (const float*)d_in[15];
    const float* kp1_w2  = (const float*)d_in[16];
    const float* kp1_b2  = (const float*)d_in[17];
    const float* tw2     = (const float*)d_in[18];
    const float* kp2_w1  = (const float*)d_in[19];
    const float* kp2_b1  = (const float*)d_in[20];
    const float* kp2_w2  = (const float*)d_in[21];
    const float* kp2_b2  = (const float*)d_in[22];
    const float* attn_sc = (const float*)d_in[23];
    const float* ffn_sc  = (const float*)d_in[24];

    float* res  = (float*)d_out;                          // [B,L,D]
    float* attn = (float*)d_out + (size_t)BB*LL*DM;       // [B,H,L,L]

    float *q, *k, *v, *t0, *x1, *x2, *gg, *hid, *xg, *wb, *xtf, *wts;
    int* kb;
    cudaGetSymbolAddress((void**)&q,   g_q);
    cudaGetSymbolAddress((void**)&k,   g_k);
    cudaGetSymbolAddress((void**)&v,   g_v);
    cudaGetSymbolAddress((void**)&t0,  g_t0);
    cudaGetSymbolAddress((void**)&x1,  g_x1);
    cudaGetSymbolAddress((void**)&x2,  g_x2);
    cudaGetSymbolAddress((void**)&gg,  g_g);
    cudaGetSymbolAddress((void**)&hid, g_hid);
    cudaGetSymbolAddress((void**)&xg,  g_xg);
    cudaGetSymbolAddress((void**)&wb,  g_w);
    cudaGetSymbolAddress((void**)&xtf, g_xtf);
    cudaGetSymbolAddress((void**)&wts, g_wts);
    cudaGetSymbolAddress((void**)&kb,  g_kk);

    float* Wq_t = wts;
    float* Wk_t = wts + 1*DM*DM;
    float* Wv_t = wts + 2*DM*DM;
    float* Wo_t = wts + 3*DM*DM;
    float* Wg_t = wts + 4*DM*DM;
    float* W1_t = wts + 5*DM*DM;
    float* W2_t = wts + 5*DM*DM + DM*DFF;

    const int szNT  = smem_size(128, 128, false);  // 75776
    const int szT   = smem_size(128, 128, true);   // 81920
    const int szAV  = smem_size(128,  64, false);  // 59392

    cudaFuncSetAttribute((const void*)gemm_cp<128,128,0,false,false,false,true >, cudaFuncAttributeMaxDynamicSharedMemorySize, szNT);
    cudaFuncSetAttribute((const void*)gemm_cp<128,128,5,true ,false,false,false>, cudaFuncAttributeMaxDynamicSharedMemorySize, szT);
    cudaFuncSetAttribute((const void*)gemm_cp<128, 64,5,false,true ,false,true >, cudaFuncAttributeMaxDynamicSharedMemorySize, szAV);
    cudaFuncSetAttribute((const void*)gemm_cp<128,128,1,false,false,false,false>, cudaFuncAttributeMaxDynamicSharedMemorySize, szNT);
    cudaFuncSetAttribute((const void*)gemm_cp<128,128,2,true ,true ,false,true >, cudaFuncAttributeMaxDynamicSharedMemorySize, szT);
    cudaFuncSetAttribute((const void*)gemm_cp<128,128,3,true ,false,false,true >, cudaFuncAttributeMaxDynamicSharedMemorySize, szT);
    cudaFuncSetAttribute((const void*)gemm_cp<128,128,4,true ,false,false,false>, cudaFuncAttributeMaxDynamicSharedMemorySize, szT);

    const dim3 blk(256);
    const long LLDM = (long)LL * DM;
    const long LL2  = (long)LL * LL;

    // ---- pre-round x and weights to tf32 ----
    cvt_tf32<<<(BLN*DM/4 + 255)/256, 256>>>((const float4*)x,       (float4*)xtf,  BLN*DM/4);
    cvt_tf32<<<(DM*DM/4 + 255)/256, 256>>>((const float4*)Wq,      (float4*)Wq_t, DM*DM/4);
    cvt_tf32<<<(DM*DM/4 + 255)/256, 256>>>((const float4*)Wk,      (float4*)Wk_t, DM*DM/4);
    cvt_tf32<<<(DM*DM/4 + 255)/256, 256>>>((const float4*)Wv,      (float4*)Wv_t, DM*DM/4);
    cvt_tf32<<<(DM*DM/4 + 255)/256, 256>>>((const float4*)Wo,      (float4*)Wo_t, DM*DM/4);
    cvt_tf32<<<(DM*DM/4 + 255)/256, 256>>>((const float4*)gate_w,  (float4*)Wg_t, DM*DM/4);
    cvt_tf32<<<(DM*DFF/4 + 255)/256, 256>>>((const float4*)conv1_w,(float4*)W1_t, DM*DFF/4);
    cvt_tf32<<<(DM*DFF/4 + 255)/256, 256>>>((const float4*)conv2_w,(float4*)W2_t, DM*DFF/4);

    // QKV projections (all operands pre-rounded; outputs rounded)
    gemm_cp<128,128,0,false,false,false,true><<<dim3(DM/128, BLN/128, 1), blk, szNT>>>(
        xtf, Wq_t, bq, nullptr, nullptr, 1.f, q, BLN, DM, DM, DM, DM, DM, 0,0,0,0,0,0);
    gemm_cp<128,128,0,false,false,false,true><<<dim3(DM/128, BLN/128, 1), blk, szNT>>>(
        xtf, Wk_t, bk, nullptr, nullptr, 1.f, k, BLN, DM, DM, DM, DM, DM, 0,0,0,0,0,0);
    gemm_cp<128,128,0,false,false,false,true><<<dim3(DM/128, BLN/128, 1), blk, szNT>>>(
        xtf, Wv_t, bv, nullptr, nullptr, 1.f, v, BLN, DM, DM, DM, DM, DM, 0,0,0,0,0,0);

    // scores: attn[b,h] = (q_bh @ k_bh^T) / 8  (fp32 out, checked later)
    gemm_cp<128,128,5,true,false,false,false><<<dim3(LL/128, LL/128, BB*HH), blk, szT>>>(
        q, k, nullptr, nullptr, nullptr, 0.125f, attn,
        LL, LL, HD, DM, DM, LL,
        LLDM, HD, LLDM, HD, 8*LL2, LL2);

    softmax1024<<<BB*HH*LL, blk>>>(attn);

    // AV: t0 = attn @ v   (A needs cvt; output rounded)
    gemm_cp<128,64,5,false,true,false,true><<<dim3(1, LL/128, BB*HH), blk, szAV>>>(
        attn, v, nullptr, nullptr, nullptr, 1.f, t0,
        LL, HD, LL, LL, DM, DM,
        8*LL2, LL2, LLDM, HD, LLDM, HD);

    // out proj + residual (x1 stays fp32)
    gemm_cp<128,128,1,false,false,false,false><<<dim3(DM/128, BLN/128, 1), blk, szNT>>>(
        t0, Wo_t, bo, x, attn_sc, 1.f, x1, BLN, DM, DM, DM, DM, DM, 0,0,0,0,0,0);

    // decomp 1
    col_mean<<<BB, 512>>>(x1, xg);
    kernel_pred<<<BB, 256>>>(xg, kp1_w1, kp1_b1, kp1_w2, kp1_b2, tw1, wb, kb);
    decomp_kern<<<dim3(LL,BB), 512>>>(x1, wb, kb, x2);

    // FFN
    gemm_cp<128,128,2,true,true,false,true><<<dim3(DM/128, BLN/128, 1), blk, szT>>>(
        x2, Wg_t, gate_b, x2, nullptr, 1.f, gg, BLN, DM, DM, DM, DM, DM, 0,0,0,0,0,0);
    gemm_cp<128,128,3,true,false,false,true><<<dim3(DFF/128, BLN/128, 1), blk, szT>>>(
        gg, W1_t, nullptr, nullptr, nullptr, 1.f, hid, BLN, DFF, DM, DM, DM, DFF, 0,0,0,0,0,0);
    gemm_cp<128,128,4,true,false,false,false><<<dim3(DM/128, BLN/128, 1), blk, szT>>>(
        hid, W2_t, nullptr, x2, ffn_sc, 1.f, x1, BLN, DM, DFF, DFF, DFF, DM, 0,0,0,0,0,0);

    // decomp 2 -> res
    col_mean<<<BB, 512>>>(x1, xg);
    kernel_pred<<<BB, 256>>>(xg, kp2_w1, kp2_b1, kp2_w2, kp2_b2, tw2, wb, kb);
    decomp_kern<<<dim3(LL,BB), 512>>>(x1, wb, kb, res);
}